// round 16
// baseline (speedup 1.0000x reference)
#include <cuda_runtime.h>
#include <cuda_fp16.h>
#include <stdint.h>
#include <math.h>

#define HD   2048
#define BDIM 8192
#define BK   64
#define NST  3
#define A_WORDS 4096            // 128 rows * 32 words (word = 2 fp16)
#define B_WORDS 2048            // 64 rows * 32 words
#define SMEM_WORDS (NST * (A_WORDS + B_WORDS))
#define SMEM_BYTES (SMEM_WORDS * 4)   // 73728

// ---------------- device scratch ----------------
__device__ __half g_S1h[(size_t)BDIM * 8192];   // [z | r | u | cand_x] fp16
__device__ __half g_S2h[(size_t)BDIM * 6144];   // [z2 | r2 | cand2] fp16
__device__ __half g_x16[(size_t)BDIM * HD];
__device__ __half g_h16[(size_t)BDIM * HD];
__device__ __half g_g16[(size_t)BDIM * HD];
__device__ __half g_hd16[(size_t)BDIM * HD];
__device__ __half g_W16[(size_t)30720 * HD];    // all weights, transposed to [N][K]

// ---------------- PTX helpers ----------------
#define CP_ASYNC(dst, src) \
    asm volatile("cp.async.cg.shared.global [%0], [%1], 16;" :: "r"(dst), "l"(src))
#define CP_COMMIT() asm volatile("cp.async.commit_group;" ::: "memory")
#define CP_WAIT(n)  asm volatile("cp.async.wait_group %0;" :: "n"(n) : "memory")

#define LDMX4(r0, r1, r2, r3, addr)                                            \
    asm volatile("ldmatrix.sync.aligned.m8n8.x4.shared.b16 {%0,%1,%2,%3}, [%4];" \
                 : "=r"(r0), "=r"(r1), "=r"(r2), "=r"(r3) : "r"(addr))

__device__ __forceinline__ void mma16f(float c[4], const uint32_t a[4], const uint32_t b[2]) {
    asm volatile(
        "mma.sync.aligned.m16n8k16.row.col.f32.f16.f16.f32 "
        "{%0,%1,%2,%3}, {%4,%5,%6,%7}, {%8,%9}, {%0,%1,%2,%3};\n"
        : "+f"(c[0]), "+f"(c[1]), "+f"(c[2]), "+f"(c[3])
        : "r"(a[0]), "r"(a[1]), "r"(a[2]), "r"(a[3]), "r"(b[0]), "r"(b[1]));
}

// swizzled word index: row = 32 words (128B), 16B chunk ch in 0..7
__device__ __forceinline__ int swz(int r, int ch) {
    return r * 32 + ((ch ^ (r & 7)) << 2);
}

__device__ __forceinline__ float sigm(float x) { return 1.f / (1.f + expf(-x)); }

// load 8 consecutive fp16 -> 8 floats (16B aligned)
__device__ __forceinline__ void ld8h(const __half* p, float* o) {
    uint4 v = *(const uint4*)p;
    const __half2* h2 = (const __half2*)&v;
#pragma unroll
    for (int q = 0; q < 4; q++) {
        float2 f = __half22float2(h2[q]);
        o[2 * q] = f.x;
        o[2 * q + 1] = f.y;
    }
}

// ---------------- GEMM args ----------------
struct GArgs {
    __half* C;
    long long ldc;
    int nA[4];
    const __half* A[4][3];
    int wrow[4][3];
    const float* bias[4][3];
};

// Tile 128x64. grid: x = M tiles (64), y = N tiles (N/64).
// blk = y>>5 (gate block), nloc = (y&31)*64
__global__ __launch_bounds__(256, 3)
void gemm_f16_kernel(const __grid_constant__ GArgs args, const __half* __restrict__ WB) {
    extern __shared__ uint32_t sm[];
    uint32_t* smA = sm;
    uint32_t* smB = sm + NST * A_WORDS;
    const uint32_t smA0 = (uint32_t)__cvta_generic_to_shared(smA);
    const uint32_t smB0 = (uint32_t)__cvta_generic_to_shared(smB);

    const int tid  = threadIdx.x;
    const int lane = tid & 31;
    const int warp = tid >> 5;
    const int wm = warp & 1;     // 2 warps along M (64 rows)
    const int wn = warp >> 1;    // 4 warps along N (16 cols)

    const int m0   = blockIdx.x << 7;
    const int blk  = blockIdx.y >> 5;
    const int nloc = (blockIdx.y & 31) << 6;
    const int nA   = args.nA[blk];
    const int iters = nA << 5;

    const __half* Ap[3];
    int wr[3];
#pragma unroll
    for (int a = 0; a < 3; a++) { Ap[a] = args.A[blk][a]; wr[a] = args.wrow[blk][a]; }

    float acc[4][2][4];
#pragma unroll
    for (int i = 0; i < 4; i++)
#pragma unroll
        for (int j = 0; j < 2; j++)
#pragma unroll
            for (int k = 0; k < 4; k++) acc[i][j][k] = 0.f;

    const int r4 = tid >> 3;     // 0..31
    const int ch = tid & 7;

    auto load_stage = [&](int it) {
        const int s = it % NST;
        const int a = it >> 5;
        const int k0 = (it & 31) << 6;
        uint32_t* dA = smA + s * A_WORDS;
        uint32_t* dB = smB + s * B_WORDS;
        const __half* Ab = Ap[a];
#pragma unroll
        for (int i = 0; i < 4; i++) {
            const int r = r4 + (i << 5);
            uint32_t dst = (uint32_t)__cvta_generic_to_shared(dA + swz(r, ch));
            CP_ASYNC(dst, Ab + (size_t)(m0 + r) * HD + k0 + ch * 8);
        }
        const size_t wbase = (size_t)(wr[a] + nloc) * HD + k0 + ch * 8;
#pragma unroll
        for (int i = 0; i < 2; i++) {
            const int r = r4 + (i << 5);
            uint32_t dst = (uint32_t)__cvta_generic_to_shared(dB + swz(r, ch));
            CP_ASYNC(dst, WB + wbase + (size_t)r * HD);
        }
        CP_COMMIT();
    };

    const int arow = wm * 64 + (lane & 15);
    const int acsel = lane >> 4;
    const int bnrow = wn * 16 + ((lane & 16) >> 1) + (lane & 7);
    const int bcsel = (lane >> 3) & 1;

    auto compute = [&](int s) {
        const uint32_t a_base = smA0 + (s * A_WORDS) * 4;
        const uint32_t b_base = smB0 + (s * B_WORDS) * 4;
#pragma unroll
        for (int ks = 0; ks < 4; ks++) {
            uint32_t af[4][4], bf[2][2];
#pragma unroll
            for (int mt = 0; mt < 4; mt++) {
                const int r = arow + mt * 16;
                const int c = (2 * ks + acsel) ^ (r & 7);
                LDMX4(af[mt][0], af[mt][1], af[mt][2], af[mt][3],
                      a_base + (r * 32 + (c << 2)) * 4);
            }
            {
                const int n = bnrow;
                const int c = (2 * ks + bcsel) ^ (n & 7);
                LDMX4(bf[0][0], bf[0][1], bf[1][0], bf[1][1],
                      b_base + (n * 32 + (c << 2)) * 4);
            }
#pragma unroll
            for (int mt = 0; mt < 4; mt++)
#pragma unroll
                for (int nt = 0; nt < 2; nt++)
                    mma16f(acc[mt][nt], af[mt], bf[nt]);
        }
    };

    load_stage(0);
    load_stage(1);
#pragma unroll 1
    for (int it = 0; it < iters; it++) {
        CP_WAIT(1);
        __syncthreads();
        if (it + 2 < iters) load_stage(it + 2);
        else CP_COMMIT();
        compute(it % NST);
    }

    // epilogue: bias + fp16 store
    const int tig = lane & 3;
    const int gid = lane >> 2;
    const int cbase = blockIdx.y << 6;
#pragma unroll
    for (int nt = 0; nt < 2; nt++) {
        const int cl = wn * 16 + nt * 8 + 2 * tig;
        float bs0 = 0.f, bs1 = 0.f;
        for (int a = 0; a < nA; a++) {
            bs0 += args.bias[blk][a][nloc + cl];
            bs1 += args.bias[blk][a][nloc + cl + 1];
        }
#pragma unroll
        for (int mt = 0; mt < 4; mt++) {
            const int r = m0 + wm * 64 + mt * 16 + gid;
            __half2 v0 = __floats2half2_rn(acc[mt][nt][0] + bs0, acc[mt][nt][1] + bs1);
            __half2 v1 = __floats2half2_rn(acc[mt][nt][2] + bs0, acc[mt][nt][3] + bs1);
            *(__half2*)(args.C + (size_t)r * args.ldc + cbase + cl) = v0;
            *(__half2*)(args.C + (size_t)(r + 8) * args.ldc + cbase + cl) = v1;
        }
    }
}

// ---------------- merged prep: weight transpose + activation conversion ----------
struct TArgs {
    const float* W[5];
    int ldw[5];
    int ntiles[5];
    int outRow[5];
};
#define WT_BLOCKS 61440
#define ACT_BLOCKS_PER 16384

__global__ void prep_kernel(const __grid_constant__ TArgs ta,
                            const float* __restrict__ x, const float* __restrict__ h,
                            const float* __restrict__ g) {
    const int bid = blockIdx.x;
    const int tid = threadIdx.x;
    if (bid < WT_BLOCKS) {
        __shared__ float t[32][33];
        int xt = bid % 960;
        const int k0 = (bid / 960) << 5;
        int m = 0;
        while (xt >= ta.ntiles[m]) { xt -= ta.ntiles[m]; m++; }
        const float* W = ta.W[m];
        const int ldw = ta.ldw[m];
        const int n0 = xt << 5;
        const int tx = tid & 31, ty = tid >> 5;
#pragma unroll
        for (int i = 0; i < 4; i++)
            t[ty + 8 * i][tx] = W[(size_t)(k0 + ty + 8 * i) * ldw + n0 + tx];
        __syncthreads();
#pragma unroll
        for (int i = 0; i < 4; i++)
            g_W16[(size_t)(ta.outRow[m] + n0 + ty + 8 * i) * HD + k0 + tx] =
                __float2half_rn(t[tx][ty + 8 * i]);
    } else {
        const int ab = bid - WT_BLOCKS;
        const int arr = ab / ACT_BLOCKS_PER;
        const int blk = ab % ACT_BLOCKS_PER;
        const float* src = (arr == 0) ? x : (arr == 1) ? h : g;
        __half* dst = (arr == 0) ? g_x16 : (arr == 1) ? g_h16 : g_g16;
        size_t i = (size_t)blk * 1024 + tid * 4;
        float4 v = *(const float4*)(src + i);
        __half2* d = (__half2*)(dst + i);
        d[0] = __floats2half2_rn(v.x, v.y);
        d[1] = __floats2half2_rn(v.z, v.w);
    }
}

// ---------------- elementwise epilogues (8 elems/thread, fp16 h/g reads) --------
__global__ void epi1_kernel(float* __restrict__ hnew) {
    size_t e0 = ((size_t)blockIdx.x * blockDim.x + threadIdx.x) * 8;
    size_t b = e0 >> 11, j = e0 & 2047;
    const __half* row = g_S1h + b * 8192 + j;
    float zp[8], rp[8], up[8], cp[8], hv[8], gv[8];
    ld8h(row, zp);
    ld8h(row + 2048, rp);
    ld8h(row + 4096, up);
    ld8h(row + 6144, cp);
    ld8h(g_h16 + e0, hv);
    ld8h(g_g16 + e0, gv);
    float hn[8];
    uint32_t hdw[4];
#pragma unroll
    for (int k = 0; k < 8; k += 2) {
        float z0 = sigm(zp[k]), r0 = sigm(rp[k]), u0 = sigm(up[k]);
        float z1 = sigm(zp[k + 1]), r1 = sigm(rp[k + 1]), u1 = sigm(up[k + 1]);
        float c0 = tanhf(cp[k] + r0 * hv[k] + u0 * gv[k]);
        float c1 = tanhf(cp[k + 1] + r1 * hv[k + 1] + u1 * gv[k + 1]);
        hn[k] = (1.f - z0) * hv[k] + z0 * c0;
        hn[k + 1] = (1.f - z1) * hv[k + 1] + z1 * c1;
        __half2 hd2 = __floats2half2_rn(hn[k] - hv[k], hn[k + 1] - hv[k + 1]);
        hdw[k >> 1] = *(uint32_t*)&hd2;
    }
    *(float4*)(hnew + e0) = make_float4(hn[0], hn[1], hn[2], hn[3]);
    *(float4*)(hnew + e0 + 4) = make_float4(hn[4], hn[5], hn[6], hn[7]);
    *(uint4*)(g_hd16 + e0) = make_uint4(hdw[0], hdw[1], hdw[2], hdw[3]);
}

__global__ void epi2_kernel(float* __restrict__ gnew) {
    size_t e0 = ((size_t)blockIdx.x * blockDim.x + threadIdx.x) * 8;
    size_t b = e0 >> 11, j = e0 & 2047;
    const __half* row = g_S2h + b * 6144 + j;
    float zp[8], rp[8], cp[8], gv[8];
    ld8h(row, zp);
    ld8h(row + 2048, rp);
    ld8h(row + 4096, cp);
    ld8h(g_g16 + e0, gv);
    float gn[8];
#pragma unroll
    for (int k = 0; k < 8; k++) {
        float z = sigm(zp[k]), r = sigm(rp[k]);
        float cand = tanhf(cp[k] + r * gv[k]);
        gn[k] = (1.f - z) * gv[k] + z * cand;
    }
    *(float4*)(gnew + e0) = make_float4(gn[0], gn[1], gn[2], gn[3]);
    *(float4*)(gnew + e0 + 4) = make_float4(gn[4], gn[5], gn[6], gn[7]);
}

// ---------------- host ----------------
extern "C" void kernel_launch(void* const* d_in, const int* in_sizes, int n_in,
                              void* d_out, int out_size) {
    (void)in_sizes; (void)n_in; (void)out_size;
    const float* x   = (const float*)d_in[0];
    const float* h   = (const float*)d_in[1];
    const float* g   = (const float*)d_in[2];
    const float* Wx  = (const float*)d_in[3];
    const float* bx  = (const float*)d_in[4];
    const float* Wh  = (const float*)d_in[5];
    const float* bh  = (const float*)d_in[6];
    const float* Wgh = (const float*)d_in[7];
    const float* bgh = (const float*)d_in[8];
    const float* Whd = (const float*)d_in[9];
    const float* bhd = (const float*)d_in[10];
    const float* Wg  = (const float*)d_in[11];
    const float* bg  = (const float*)d_in[12];

    float* out  = (float*)d_out;
    float* hnew = out;
    float* gnew = out + (size_t)BDIM * HD;

    void *pS1, *pS2, *pX, *pH, *pG, *pHd, *pW;
    cudaGetSymbolAddress(&pS1, g_S1h);
    cudaGetSymbolAddress(&pS2, g_S2h);
    cudaGetSymbolAddress(&pX, g_x16);
    cudaGetSymbolAddress(&pH, g_h16);
    cudaGetSymbolAddress(&pG, g_g16);
    cudaGetSymbolAddress(&pHd, g_hd16);
    cudaGetSymbolAddress(&pW, g_W16);

    cudaFuncSetAttribute(gemm_f16_kernel, cudaFuncAttributeMaxDynamicSharedMemorySize,
                         SMEM_BYTES);

    const int H = HD;
    const int RWx = 0, RWh = 8192, RWgh = 14336, RWhd = 20480, RWg = 26624;

    // 1) merged prep: weights transpose + activation conversion
    {
        TArgs ta;
        const float* Ws[5] = {Wx, Wh, Wgh, Whd, Wg};
        int lds[5] = {4 * H, 3 * H, 3 * H, 3 * H, 2 * H};
        int nts[5] = {256, 192, 192, 192, 128};
        int orow[5] = {RWx, RWh, RWgh, RWhd, RWg};
        for (int i = 0; i < 5; i++) {
            ta.W[i] = Ws[i]; ta.ldw[i] = lds[i]; ta.ntiles[i] = nts[i]; ta.outRow[i] = orow[i];
        }
        prep_kernel<<<WT_BLOCKS + 3 * ACT_BLOCKS_PER, 256>>>(ta, x, h, g);
    }

    const __half* x16 = (const __half*)pX;
    const __half* h16 = (const __half*)pH;
    const __half* g16 = (const __half*)pG;
    const __half* hd16 = (const __half*)pHd;

    // 2) stage-1 GEMM: S1h = [z | r | u | cand_x], ldc 8192 (fp16), grid (64,128)
    {
        GArgs a;
        a.C = (__half*)pS1; a.ldc = 8192;
        int nA[4] = {3, 3, 3, 1};
        const __half* A[4][3] = {{x16, h16, g16}, {x16, h16, g16}, {x16, h16, g16},
                                 {x16, x16, x16}};
        int WR[4][3] = {{RWx, RWh, RWgh},
                        {RWx + H, RWh + H, RWgh + H},
                        {RWx + 3 * H, RWh + 2 * H, RWgh + 2 * H},
                        {RWx + 2 * H, 0, 0}};
        const float* Bp[4][3] = {{bx, bh, bgh},
                                 {bx + H, bh + H, bgh + H},
                                 {bx + 3 * H, bh + 2 * H, bgh + 2 * H},
                                 {bx + 2 * H, bx, bx}};
        for (int i = 0; i < 4; i++) {
            a.nA[i] = nA[i];
            for (int j = 0; j < 3; j++) {
                a.A[i][j] = A[i][j]; a.wrow[i][j] = WR[i][j]; a.bias[i][j] = Bp[i][j];
            }
        }
        gemm_f16_kernel<<<dim3(64, 128), 256, SMEM_BYTES>>>(a, (const __half*)pW);
    }

    unsigned epiBlocks = (unsigned)(((size_t)BDIM * HD / 8) / 256);
    epi1_kernel<<<epiBlocks, 256>>>(hnew);

    // 3) stage-2 GEMM: S2h = [z2 | r2 | cand2], ldc 6144 (fp16), grid (64,96)
    {
        GArgs a;
        a.C = (__half*)pS2; a.ldc = 6144;
        int nA[4] = {2, 2, 1, 1};
        const __half* A[4][3] = {{hd16, g16, hd16}, {hd16, g16, hd16},
                                 {hd16, hd16, hd16}, {hd16, hd16, hd16}};
        int WR[4][3] = {{RWhd, RWg, 0},
                        {RWhd + H, RWg + H, 0},
                        {RWhd + 2 * H, 0, 0},
                        {0, 0, 0}};
        const float* Bp[4][3] = {{bhd, bg, bhd},
                                 {bhd + H, bg + H, bhd},
                                 {bhd + 2 * H, bhd, bhd},
                                 {bhd, bhd, bhd}};
        for (int i = 0; i < 4; i++) {
            a.nA[i] = nA[i];
            for (int j = 0; j < 3; j++) {
                a.A[i][j] = A[i][j]; a.wrow[i][j] = WR[i][j]; a.bias[i][j] = Bp[i][j];
            }
        }
        gemm_f16_kernel<<<dim3(64, 96), 256, SMEM_BYTES>>>(a, (const __half*)pW);
    }

    epi2_kernel<<<epiBlocks, 256>>>(gnew);
}

// round 17
// speedup vs baseline: 1.2604x; 1.2604x over previous
#include <cuda_runtime.h>
#include <cuda_fp16.h>
#include <stdint.h>
#include <math.h>

#define HD   2048
#define BDIM 8192
#define BK   64
#define NST  3
#define A_WORDS 4096            // 128 rows * 32 words (word = 2 fp16)
#define B_WORDS 4096
#define SMEM_WORDS (NST * (A_WORDS + B_WORDS))
#define SMEM_BYTES (SMEM_WORDS * 4)   // 98304

// ---------------- device scratch ----------------
__device__ __half g_S1h[(size_t)BDIM * 8192];   // [z | r | u | cand_x] fp16
__device__ __half g_S2h[(size_t)BDIM * 6144];   // [z2 | r2 | cand2] fp16
__device__ __half g_x16[(size_t)BDIM * HD];
__device__ __half g_h16[(size_t)BDIM * HD];
__device__ __half g_g16[(size_t)BDIM * HD];
__device__ __half g_hd16[(size_t)BDIM * HD];
__device__ __half g_W16[(size_t)30720 * HD];    // all weights, transposed to [N][K]

// ---------------- PTX helpers ----------------
#define CP_ASYNC(dst, src) \
    asm volatile("cp.async.cg.shared.global [%0], [%1], 16;" :: "r"(dst), "l"(src))
#define CP_COMMIT() asm volatile("cp.async.commit_group;" ::: "memory")
#define CP_WAIT(n)  asm volatile("cp.async.wait_group %0;" :: "n"(n) : "memory")

#define LDMX4(r0, r1, r2, r3, addr)                                            \
    asm volatile("ldmatrix.sync.aligned.m8n8.x4.shared.b16 {%0,%1,%2,%3}, [%4];" \
                 : "=r"(r0), "=r"(r1), "=r"(r2), "=r"(r3) : "r"(addr))

__device__ __forceinline__ void mma16f(float c[4], const uint32_t a[4], const uint32_t b[2]) {
    asm volatile(
        "mma.sync.aligned.m16n8k16.row.col.f32.f16.f16.f32 "
        "{%0,%1,%2,%3}, {%4,%5,%6,%7}, {%8,%9}, {%0,%1,%2,%3};\n"
        : "+f"(c[0]), "+f"(c[1]), "+f"(c[2]), "+f"(c[3])
        : "r"(a[0]), "r"(a[1]), "r"(a[2]), "r"(a[3]), "r"(b[0]), "r"(b[1]));
}

// swizzled word index: row = 32 words (128B), 16B chunk ch in 0..7
__device__ __forceinline__ int swz(int r, int ch) {
    return r * 32 + ((ch ^ (r & 7)) << 2);
}

__device__ __forceinline__ float sigm(float x) { return 1.f / (1.f + expf(-x)); }

// load 8 consecutive fp16 -> 8 floats (16B aligned)
__device__ __forceinline__ void ld8h(const __half* p, float* o) {
    uint4 v = *(const uint4*)p;
    const __half2* h2 = (const __half2*)&v;
#pragma unroll
    for (int q = 0; q < 4; q++) {
        float2 f = __half22float2(h2[q]);
        o[2 * q] = f.x;
        o[2 * q + 1] = f.y;
    }
}

// ---------------- GEMM args ----------------
struct GArgs {
    __half* C;
    long long ldc;
    int nA[4];
    const __half* A[4][3];
    int wrow[4][3];
    const float* bias[4][3];
};

// grid: x = M tiles (64), y = N tiles. blk = y>>4 (gate block), nloc = (y&15)*128
__global__ __launch_bounds__(256, 2)
void gemm_f16_kernel(const __grid_constant__ GArgs args, const __half* __restrict__ WB) {
    extern __shared__ uint32_t sm[];
    uint32_t* smA = sm;
    uint32_t* smB = sm + NST * A_WORDS;
    const uint32_t smA0 = (uint32_t)__cvta_generic_to_shared(smA);
    const uint32_t smB0 = (uint32_t)__cvta_generic_to_shared(smB);

    const int tid  = threadIdx.x;
    const int lane = tid & 31;
    const int warp = tid >> 5;
    const int wm = warp & 1;
    const int wn = warp >> 1;

    const int m0   = blockIdx.x << 7;
    const int blk  = blockIdx.y >> 4;
    const int nloc = (blockIdx.y & 15) << 7;
    const int nA   = args.nA[blk];
    const int iters = nA << 5;

    const __half* Ap[3];
    int wr[3];
#pragma unroll
    for (int a = 0; a < 3; a++) { Ap[a] = args.A[blk][a]; wr[a] = args.wrow[blk][a]; }

    float acc[4][4][4];
#pragma unroll
    for (int i = 0; i < 4; i++)
#pragma unroll
        for (int j = 0; j < 4; j++)
#pragma unroll
            for (int k = 0; k < 4; k++) acc[i][j][k] = 0.f;

    const int r4 = tid >> 3;
    const int ch = tid & 7;

    // load stage s with data for k-iteration `it`
    auto load_stage = [&](int it, int s) {
        const int a = it >> 5;
        const int k0 = (it & 31) << 6;
        uint32_t* dA = smA + s * A_WORDS;
        uint32_t* dB = smB + s * B_WORDS;
        const __half* Ab = Ap[a];
#pragma unroll
        for (int i = 0; i < 4; i++) {
            const int r = r4 + (i << 5);
            uint32_t dst = (uint32_t)__cvta_generic_to_shared(dA + swz(r, ch));
            CP_ASYNC(dst, Ab + (size_t)(m0 + r) * HD + k0 + ch * 8);
        }
        const size_t wbase = (size_t)(wr[a] + nloc) * HD + k0 + ch * 8;
#pragma unroll
        for (int i = 0; i < 4; i++) {
            const int r = r4 + (i << 5);
            uint32_t dst = (uint32_t)__cvta_generic_to_shared(dB + swz(r, ch));
            CP_ASYNC(dst, WB + wbase + (size_t)r * HD);
        }
        CP_COMMIT();
    };

    const int arow = wm * 64 + (lane & 15);
    const int acsel = lane >> 4;
    const int bnrow = wn * 32 + ((lane & 16) >> 1) + (lane & 7);
    const int bcsel = (lane >> 3) & 1;

    auto compute = [&](int s) {
        const uint32_t a_base = smA0 + (s * A_WORDS) * 4;
        const uint32_t b_base = smB0 + (s * B_WORDS) * 4;
#pragma unroll
        for (int ks = 0; ks < 4; ks++) {
            uint32_t af[4][4], bf[4][2];
#pragma unroll
            for (int mt = 0; mt < 4; mt++) {
                const int r = arow + mt * 16;
                const int c = (2 * ks + acsel) ^ (r & 7);
                LDMX4(af[mt][0], af[mt][1], af[mt][2], af[mt][3],
                      a_base + (r * 32 + (c << 2)) * 4);
            }
#pragma unroll
            for (int np = 0; np < 2; np++) {
                const int n = bnrow + np * 16;
                const int c = (2 * ks + bcsel) ^ (n & 7);
                LDMX4(bf[2 * np][0], bf[2 * np][1], bf[2 * np + 1][0], bf[2 * np + 1][1],
                      b_base + (n * 32 + (c << 2)) * 4);
            }
#pragma unroll
            for (int mt = 0; mt < 4; mt++)
#pragma unroll
                for (int nt = 0; nt < 4; nt++)
                    mma16f(acc[mt][nt], af[mt], bf[nt]);
        }
    };

    load_stage(0, 0);
    load_stage(1, 1);

    // cyclic stage counters (no modulo in the hot loop)
    int sc = 0;   // compute stage for iteration it
    int sl = 2;   // load stage for iteration it+2
#pragma unroll 1
    for (int it = 0; it < iters; it++) {
        CP_WAIT(1);
        __syncthreads();
        if (it + 2 < iters) load_stage(it + 2, sl);
        else CP_COMMIT();
        compute(sc);
        sc = (sc == NST - 1) ? 0 : sc + 1;
        sl = (sl == NST - 1) ? 0 : sl + 1;
    }

    // epilogue: bias + fp16 store
    const int tig = lane & 3;
    const int gid = lane >> 2;
    const int cbase = blockIdx.y << 7;
#pragma unroll
    for (int nt = 0; nt < 4; nt++) {
        const int cl = wn * 32 + nt * 8 + 2 * tig;
        float bs0 = 0.f, bs1 = 0.f;
        for (int a = 0; a < nA; a++) {
            bs0 += args.bias[blk][a][nloc + cl];
            bs1 += args.bias[blk][a][nloc + cl + 1];
        }
#pragma unroll
        for (int mt = 0; mt < 4; mt++) {
            const int r = m0 + wm * 64 + mt * 16 + gid;
            __half2 v0 = __floats2half2_rn(acc[mt][nt][0] + bs0, acc[mt][nt][1] + bs1);
            __half2 v1 = __floats2half2_rn(acc[mt][nt][2] + bs0, acc[mt][nt][3] + bs1);
            *(__half2*)(args.C + (size_t)r * args.ldc + cbase + cl) = v0;
            *(__half2*)(args.C + (size_t)(r + 8) * args.ldc + cbase + cl) = v1;
        }
    }
}

// ---------------- merged prep: weight transpose + activation conversion ----------
struct TArgs {
    const float* W[5];
    int ldw[5];
    int ntiles[5];
    int outRow[5];
};
#define WT_BLOCKS 61440
#define ACT_BLOCKS_PER 16384

__global__ void prep_kernel(const __grid_constant__ TArgs ta,
                            const float* __restrict__ x, const float* __restrict__ h,
                            const float* __restrict__ g) {
    const int bid = blockIdx.x;
    const int tid = threadIdx.x;
    if (bid < WT_BLOCKS) {
        __shared__ float t[32][33];
        int xt = bid % 960;
        const int k0 = (bid / 960) << 5;
        int m = 0;
        while (xt >= ta.ntiles[m]) { xt -= ta.ntiles[m]; m++; }
        const float* W = ta.W[m];
        const int ldw = ta.ldw[m];
        const int n0 = xt << 5;
        const int tx = tid & 31, ty = tid >> 5;
#pragma unroll
        for (int i = 0; i < 4; i++)
            t[ty + 8 * i][tx] = W[(size_t)(k0 + ty + 8 * i) * ldw + n0 + tx];
        __syncthreads();
#pragma unroll
        for (int i = 0; i < 4; i++)
            g_W16[(size_t)(ta.outRow[m] + n0 + ty + 8 * i) * HD + k0 + tx] =
                __float2half_rn(t[tx][ty + 8 * i]);
    } else {
        const int ab = bid - WT_BLOCKS;
        const int arr = ab / ACT_BLOCKS_PER;
        const int blk = ab % ACT_BLOCKS_PER;
        const float* src = (arr == 0) ? x : (arr == 1) ? h : g;
        __half* dst = (arr == 0) ? g_x16 : (arr == 1) ? g_h16 : g_g16;
        size_t i = (size_t)blk * 1024 + tid * 4;
        float4 v = *(const float4*)(src + i);
        __half2* d = (__half2*)(dst + i);
        d[0] = __floats2half2_rn(v.x, v.y);
        d[1] = __floats2half2_rn(v.z, v.w);
    }
}

// ---------------- elementwise epilogues (8 elems/thread, fp16 h/g reads) --------
__global__ void epi1_kernel(float* __restrict__ hnew) {
    size_t e0 = ((size_t)blockIdx.x * blockDim.x + threadIdx.x) * 8;
    size_t b = e0 >> 11, j = e0 & 2047;
    const __half* row = g_S1h + b * 8192 + j;
    float zp[8], rp[8], up[8], cp[8], hv[8], gv[8];
    ld8h(row, zp);
    ld8h(row + 2048, rp);
    ld8h(row + 4096, up);
    ld8h(row + 6144, cp);
    ld8h(g_h16 + e0, hv);
    ld8h(g_g16 + e0, gv);
    float hn[8];
    uint32_t hdw[4];
#pragma unroll
    for (int k = 0; k < 8; k += 2) {
        float z0 = sigm(zp[k]), r0 = sigm(rp[k]), u0 = sigm(up[k]);
        float z1 = sigm(zp[k + 1]), r1 = sigm(rp[k + 1]), u1 = sigm(up[k + 1]);
        float c0 = tanhf(cp[k] + r0 * hv[k] + u0 * gv[k]);
        float c1 = tanhf(cp[k + 1] + r1 * hv[k + 1] + u1 * gv[k + 1]);
        hn[k] = (1.f - z0) * hv[k] + z0 * c0;
        hn[k + 1] = (1.f - z1) * hv[k + 1] + z1 * c1;
        __half2 hd2 = __floats2half2_rn(hn[k] - hv[k], hn[k + 1] - hv[k + 1]);
        hdw[k >> 1] = *(uint32_t*)&hd2;
    }
    *(float4*)(hnew + e0) = make_float4(hn[0], hn[1], hn[2], hn[3]);
    *(float4*)(hnew + e0 + 4) = make_float4(hn[4], hn[5], hn[6], hn[7]);
    *(uint4*)(g_hd16 + e0) = make_uint4(hdw[0], hdw[1], hdw[2], hdw[3]);
}

__global__ void epi2_kernel(float* __restrict__ gnew) {
    size_t e0 = ((size_t)blockIdx.x * blockDim.x + threadIdx.x) * 8;
    size_t b = e0 >> 11, j = e0 & 2047;
    const __half* row = g_S2h + b * 6144 + j;
    float zp[8], rp[8], cp[8], gv[8];
    ld8h(row, zp);
    ld8h(row + 2048, rp);
    ld8h(row + 4096, cp);
    ld8h(g_g16 + e0, gv);
    float gn[8];
#pragma unroll
    for (int k = 0; k < 8; k++) {
        float z = sigm(zp[k]), r = sigm(rp[k]);
        float cand = tanhf(cp[k] + r * gv[k]);
        gn[k] = (1.f - z) * gv[k] + z * cand;
    }
    *(float4*)(gnew + e0) = make_float4(gn[0], gn[1], gn[2], gn[3]);
    *(float4*)(gnew + e0 + 4) = make_float4(gn[4], gn[5], gn[6], gn[7]);
}

// ---------------- host ----------------
extern "C" void kernel_launch(void* const* d_in, const int* in_sizes, int n_in,
                              void* d_out, int out_size) {
    (void)in_sizes; (void)n_in; (void)out_size;
    const float* x   = (const float*)d_in[0];
    const float* h   = (const float*)d_in[1];
    const float* g   = (const float*)d_in[2];
    const float* Wx  = (const float*)d_in[3];
    const float* bx  = (const float*)d_in[4];
    const float* Wh  = (const float*)d_in[5];
    const float* bh  = (const float*)d_in[6];
    const float* Wgh = (const float*)d_in[7];
    const float* bgh = (const float*)d_in[8];
    const float* Whd = (const float*)d_in[9];
    const float* bhd = (const float*)d_in[10];
    const float* Wg  = (const float*)d_in[11];
    const float* bg  = (const float*)d_in[12];

    float* out  = (float*)d_out;
    float* hnew = out;
    float* gnew = out + (size_t)BDIM * HD;

    void *pS1, *pS2, *pX, *pH, *pG, *pHd, *pW;
    cudaGetSymbolAddress(&pS1, g_S1h);
    cudaGetSymbolAddress(&pS2, g_S2h);
    cudaGetSymbolAddress(&pX, g_x16);
    cudaGetSymbolAddress(&pH, g_h16);
    cudaGetSymbolAddress(&pG, g_g16);
    cudaGetSymbolAddress(&pHd, g_hd16);
    cudaGetSymbolAddress(&pW, g_W16);

    cudaFuncSetAttribute(gemm_f16_kernel, cudaFuncAttributeMaxDynamicSharedMemorySize,
                         SMEM_BYTES);

    const int H = HD;
    const int RWx = 0, RWh = 8192, RWgh = 14336, RWhd = 20480, RWg = 26624;

    // 1) merged prep: weights transpose + activation conversion
    {
        TArgs ta;
        const float* Ws[5] = {Wx, Wh, Wgh, Whd, Wg};
        int lds[5] = {4 * H, 3 * H, 3 * H, 3 * H, 2 * H};
        int nts[5] = {256, 192, 192, 192, 128};
        int orow[5] = {RWx, RWh, RWgh, RWhd, RWg};
        for (int i = 0; i < 5; i++) {
            ta.W[i] = Ws[i]; ta.ldw[i] = lds[i]; ta.ntiles[i] = nts[i]; ta.outRow[i] = orow[i];
        }
        prep_kernel<<<WT_BLOCKS + 3 * ACT_BLOCKS_PER, 256>>>(ta, x, h, g);
    }

    const __half* x16 = (const __half*)pX;
    const __half* h16 = (const __half*)pH;
    const __half* g16 = (const __half*)pG;
    const __half* hd16 = (const __half*)pHd;

    // 2) stage-1 GEMM: S1h = [z | r | u | cand_x], ldc 8192 (fp16)
    {
        GArgs a;
        a.C = (__half*)pS1; a.ldc = 8192;
        int nA[4] = {3, 3, 3, 1};
        const __half* A[4][3] = {{x16, h16, g16}, {x16, h16, g16}, {x16, h16, g16},
                                 {x16, x16, x16}};
        int WR[4][3] = {{RWx, RWh, RWgh},
                        {RWx + H, RWh + H, RWgh + H},
                        {RWx + 3 * H, RWh + 2 * H, RWgh + 2 * H},
                        {RWx + 2 * H, 0, 0}};
        const float* Bp[4][3] = {{bx, bh, bgh},
                                 {bx + H, bh + H, bgh + H},
                                 {bx + 3 * H, bh + 2 * H, bgh + 2 * H},
                                 {bx + 2 * H, bx, bx}};
        for (int i = 0; i < 4; i++) {
            a.nA[i] = nA[i];
            for (int j = 0; j < 3; j++) {
                a.A[i][j] = A[i][j]; a.wrow[i][j] = WR[i][j]; a.bias[i][j] = Bp[i][j];
            }
        }
        gemm_f16_kernel<<<dim3(64, 64), 256, SMEM_BYTES>>>(a, (const __half*)pW);
    }

    unsigned epiBlocks = (unsigned)(((size_t)BDIM * HD / 8) / 256);
    epi1_kernel<<<epiBlocks, 256>>>(hnew);

    // 3) stage-2 GEMM: S2h = [z2 | r2 | cand2], ldc 6144 (fp16)
    {
        GArgs a;
        a.C = (__half*)pS2; a.ldc = 6144;
        int nA[4] = {2, 2, 1, 1};
        const __half* A[4][3] = {{hd16, g16, hd16}, {hd16, g16, hd16},
                                 {hd16, hd16, hd16}, {hd16, hd16, hd16}};
        int WR[4][3] = {{RWhd, RWg, 0},
                        {RWhd + H, RWg + H, 0},
                        {RWhd + 2 * H, 0, 0},
                        {0, 0, 0}};
        const float* Bp[4][3] = {{bhd, bg, bhd},
                                 {bhd + H, bg + H, bhd},
                                 {bhd + 2 * H, bhd, bhd},
                                 {bhd, bhd, bhd}};
        for (int i = 0; i < 4; i++) {
            a.nA[i] = nA[i];
            for (int j = 0; j < 3; j++) {
                a.A[i][j] = A[i][j]; a.wrow[i][j] = WR[i][j]; a.bias[i][j] = Bp[i][j];
            }
        }
        gemm_f16_kernel<<<dim3(64, 48), 256, SMEM_BYTES>>>(a, (const __half*)pW);
    }

    epi2_kernel<<<epiBlocks, 256>>>(gnew);
}